// round 1
// baseline (speedup 1.0000x reference)
#include <cuda_runtime.h>

// Problem constants
#define Bb 4
#define Cc 64
#define NA 25
#define HW 4096
#define Dd 64
#define Oo 192

// Scratch (device globals -- no runtime allocation allowed)
__device__ float g_qkv[(size_t)Bb * Oo * NA * HW];     // 78,643,200 floats = 315 MB
__device__ float g_part[Bb * Dd * 675];                // per-(b,d) partial S (625) + nq2 (25) + nk2 (25)
__device__ float g_att[Bb * NA * NA];

// ---------------------------------------------------------------------------
// K1: qkv[b,o,n,p] = sum_c W[o,c] * x[b,c,n,p]
// Block: (ptile of 256 px) x (otile of 64 o), fixed (b,n). 256 threads.
// Thread computes 8 o x 8 px with smem tiles: per c-step 16 LDS / 64 FMA.
// ---------------------------------------------------------------------------
__global__ __launch_bounds__(256) void k_qkv(const float* __restrict__ x,
                                             const float* __restrict__ Wm) {
    const int pt = blockIdx.x;          // 0..15
    const int n  = blockIdx.y % NA;     // 0..24
    const int ot = blockIdx.y / NA;     // 0..2
    const int b  = blockIdx.z;          // 0..3

    __shared__ float xs[16][256];
    __shared__ float ws[64][16];

    const int tid  = threadIdx.x;
    const int ptid = tid & 31;          // px lane within 32
    const int otid = tid >> 5;          // o group 0..7

    const float* xb = x + (size_t)b * Cc * NA * HW + (size_t)n * HW + pt * 256;

    float acc[8][8];
#pragma unroll
    for (int i = 0; i < 8; i++)
#pragma unroll
        for (int j = 0; j < 8; j++) acc[i][j] = 0.0f;

    for (int kc = 0; kc < Cc; kc += 16) {
        __syncthreads();
        // load x tile: 16 channels x 256 px (coalesced: 256 consecutive floats/row)
#pragma unroll
        for (int r = 0; r < 16; r++)
            xs[r][tid] = xb[(size_t)(kc + r) * (NA * HW) + tid];
        // load W tile: 64 o x 16 c
#pragma unroll
        for (int i = 0; i < 4; i++) {
            int idx = tid + i * 256;    // 0..1023
            int ol = idx >> 4, cl = idx & 15;
            ws[ol][cl] = Wm[(ot * 64 + ol) * Cc + kc + cl];
        }
        __syncthreads();

#pragma unroll
        for (int cl = 0; cl < 16; cl++) {
            float xv[8], wv[8];
#pragma unroll
            for (int jp = 0; jp < 8; jp++) xv[jp] = xs[cl][ptid + 32 * jp];
#pragma unroll
            for (int jo = 0; jo < 8; jo++) wv[jo] = ws[otid * 8 + jo][cl];
#pragma unroll
            for (int jo = 0; jo < 8; jo++)
#pragma unroll
                for (int jp = 0; jp < 8; jp++)
                    acc[jo][jp] += wv[jo] * xv[jp];
        }
    }

    float* ob = g_qkv + (((size_t)b * Oo + ot * 64) * NA + n) * HW + pt * 256;
#pragma unroll
    for (int jo = 0; jo < 8; jo++)
#pragma unroll
        for (int jp = 0; jp < 8; jp++)
            ob[(size_t)(otid * 8 + jo) * (NA * HW) + 32 * jp + ptid] = acc[jo][jp];
}

// ---------------------------------------------------------------------------
// K2: per (b,d) block: partial S[n,m] = sum_p q[d,n,p]*k[d,m,p], plus
// squared-norm partials nq2[n], nk2[m]. Deterministic: slice reduction in
// smem (fixed order), partial written to g_part; cross-d reduction in K3.
// 250 active threads = 25 (5x5 pair tiles) x 10 p-slices.
// ---------------------------------------------------------------------------
__global__ __launch_bounds__(256) void k_gram() {
    const int d = blockIdx.x;           // 0..63
    const int b = blockIdx.y;           // 0..3

    const float* qp = g_qkv + ((size_t)b * Oo + d) * (NA * HW);
    const float* kp = g_qkv + ((size_t)b * Oo + 64 + d) * (NA * HW);

    __shared__ float pool[2 * 25 * 136];          // 6800 floats; overlaid by sred (6750) after loop
    float* qs = pool;                              // [25][136]
    float* ks = pool + 25 * 136;                   // [25][136]

    const int tid   = threadIdx.x;
    const int tile  = tid / 10;                    // 0..24 (valid when tid<250)
    const int slice = tid % 10;
    const int tr = tile / 5, tc = tile % 5;
    const bool active = (tid < 250);

    float acc[5][5];
#pragma unroll
    for (int i = 0; i < 5; i++)
#pragma unroll
        for (int j = 0; j < 5; j++) acc[i][j] = 0.0f;
    float accq[5] = {0, 0, 0, 0, 0};
    float acck[5] = {0, 0, 0, 0, 0};

    for (int p0 = 0; p0 < HW; p0 += 128) {
        __syncthreads();
        for (int i = tid; i < 25 * 128; i += 256) {
            int r = i >> 7, c = i & 127;
            qs[r * 136 + c] = qp[(size_t)r * HW + p0 + c];
            ks[r * 136 + c] = kp[(size_t)r * HW + p0 + c];
        }
        __syncthreads();
        if (active) {
            for (int pp = slice; pp < 128; pp += 10) {
                float qv[5], kv[5];
#pragma unroll
                for (int i = 0; i < 5; i++) qv[i] = qs[(tr * 5 + i) * 136 + pp];
#pragma unroll
                for (int j = 0; j < 5; j++) kv[j] = ks[(tc * 5 + j) * 136 + pp];
#pragma unroll
                for (int i = 0; i < 5; i++)
#pragma unroll
                    for (int j = 0; j < 5; j++)
                        acc[i][j] += qv[i] * kv[j];
                if (tc == 0) {
#pragma unroll
                    for (int i = 0; i < 5; i++) accq[i] += qv[i] * qv[i];
                }
                if (tr == 0) {
#pragma unroll
                    for (int j = 0; j < 5; j++) acck[j] += kv[j] * kv[j];
                }
            }
        }
    }

    __syncthreads();
    float* sred = pool;                            // [675][10] overlay
    if (active) {
#pragma unroll
        for (int i = 0; i < 5; i++)
#pragma unroll
            for (int j = 0; j < 5; j++)
                sred[((tr * 5 + i) * 25 + (tc * 5 + j)) * 10 + slice] = acc[i][j];
        if (tc == 0) {
#pragma unroll
            for (int i = 0; i < 5; i++)
                sred[(625 + tr * 5 + i) * 10 + slice] = accq[i];
        }
        if (tr == 0) {
#pragma unroll
            for (int j = 0; j < 5; j++)
                sred[(650 + tc * 5 + j) * 10 + slice] = acck[j];
        }
    }
    __syncthreads();

    float* gp = g_part + ((size_t)b * Dd + d) * 675;
    for (int e = tid; e < 675; e += 256) {
        float s = 0.0f;
#pragma unroll
        for (int sl = 0; sl < 10; sl++) s += sred[e * 10 + sl];
        gp[e] = s;
    }
}

// ---------------------------------------------------------------------------
// K3: reduce 64 d-partials per batch (fixed order -> deterministic), then
// normalized softmax: att = softmax( S[n,m] / (max(||q_n||,eps)*max(||k_m||,eps)) )
// ---------------------------------------------------------------------------
__global__ __launch_bounds__(256) void k_soft() {
    __shared__ float sS[Bb * 675];
    const int tid = threadIdx.x;

    for (int e = tid; e < Bb * 675; e += 256) {
        int b = e / 675, r = e % 675;
        const float* gp = g_part + (size_t)b * Dd * 675 + r;
        float s = 0.0f;
#pragma unroll 8
        for (int dd = 0; dd < Dd; dd++) s += gp[(size_t)dd * 675];
        sS[e] = s;
    }
    __syncthreads();

    if (tid < Bb * NA) {
        int b = tid / NA, n = tid % NA;
        const float* Sb = sS + b * 675;
        float qn = fmaxf(sqrtf(fmaxf(Sb[625 + n], 0.0f)), 1e-12f);
        float v[25];
        float mx = -3.0e38f;
#pragma unroll
        for (int m = 0; m < 25; m++) {
            float kn = fmaxf(sqrtf(fmaxf(Sb[650 + m], 0.0f)), 1e-12f);
            v[m] = Sb[n * 25 + m] / (qn * kn);
            mx = fmaxf(mx, v[m]);
        }
        float sum = 0.0f;
#pragma unroll
        for (int m = 0; m < 25; m++) {
            v[m] = expf(v[m] - mx);
            sum += v[m];
        }
        float inv = 1.0f / sum;
#pragma unroll
        for (int m = 0; m < 25; m++)
            g_att[(b * NA + n) * NA + m] = v[m] * inv;
    }
}

// ---------------------------------------------------------------------------
// K4: out[b,d,n,p] = sum_m att[b,n,m] * v[b,d,m,p]
// Block: (b, d, ptile of 1024 px). Thread: float4 (4 px) x 5-row n-blocking.
// ---------------------------------------------------------------------------
__global__ __launch_bounds__(256) void k_out(float* __restrict__ out) {
    const int pt = blockIdx.x;          // 0..3
    const int d  = blockIdx.y;          // 0..63
    const int b  = blockIdx.z;          // 0..3

    __shared__ float atts[625];
    const int tid = threadIdx.x;
    for (int i = tid; i < 625; i += 256) atts[i] = g_att[b * 625 + i];
    __syncthreads();

    const int px = pt * 1024 + tid * 4;
    const float4* vp = (const float4*)(g_qkv + (((size_t)b * Oo + 128 + d) * NA) * HW + px);
    float4* op = (float4*)(out + (((size_t)b * Dd + d) * NA) * HW + px);

    for (int ng = 0; ng < 5; ng++) {
        float4 acc[5];
#pragma unroll
        for (int i = 0; i < 5; i++) acc[i] = make_float4(0.f, 0.f, 0.f, 0.f);
#pragma unroll
        for (int m = 0; m < 25; m++) {
            float4 vv = vp[m * (HW / 4)];
#pragma unroll
            for (int i = 0; i < 5; i++) {
                float a = atts[(ng * 5 + i) * 25 + m];
                acc[i].x += a * vv.x;
                acc[i].y += a * vv.y;
                acc[i].z += a * vv.z;
                acc[i].w += a * vv.w;
            }
        }
#pragma unroll
        for (int i = 0; i < 5; i++)
            op[(ng * 5 + i) * (HW / 4)] = acc[i];
    }
}

// ---------------------------------------------------------------------------
extern "C" void kernel_launch(void* const* d_in, const int* in_sizes, int n_in,
                              void* d_out, int out_size) {
    const float* x  = (const float*)d_in[0];
    const float* Wm = (const float*)d_in[1];
    float* out = (float*)d_out;

    k_qkv<<<dim3(16, 75, 4), 256>>>(x, Wm);   // 4800 blocks
    k_gram<<<dim3(64, 4), 256>>>();           // 256 blocks
    k_soft<<<1, 256>>>();
    k_out<<<dim3(4, 64, 4), 256>>>(out);      // 1024 blocks
}

// round 2
// speedup vs baseline: 1.0109x; 1.0109x over previous
#include <cuda_runtime.h>

// Problem constants
#define Bb 4
#define Cc 64
#define NA 25
#define HW 4096
#define Dd 64
#define Oo 192

// Scratch (device globals -- no runtime allocation allowed)
__device__ float g_qkv[(size_t)Bb * Oo * NA * HW];     // 78,643,200 floats = 315 MB
__device__ float g_part[Bb * Dd * 675];                // per-(b,d) partial S (625) + nq2 (25) + nk2 (25)
__device__ float g_att[Bb * NA * NA];

// ---------------------------------------------------------------------------
// K1: qkv[b,o,n,p] = sum_c W[o,c] * x[b,c,n,p]
// Block: (ptile of 256 px) x (otile of 64 o), fixed (b,n). 256 threads.
// Thread computes 8 o x 8 px with smem tiles: per c-step 16 LDS / 64 FMA.
// ---------------------------------------------------------------------------
__global__ __launch_bounds__(256) void k_qkv(const float* __restrict__ x,
                                             const float* __restrict__ Wm) {
    const int pt = blockIdx.x;          // 0..15
    const int n  = blockIdx.y % NA;     // 0..24
    const int ot = blockIdx.y / NA;     // 0..2
    const int b  = blockIdx.z;          // 0..3

    __shared__ float xs[16][256];
    __shared__ float ws[64][16];

    const int tid  = threadIdx.x;
    const int ptid = tid & 31;          // px lane within 32
    const int otid = tid >> 5;          // o group 0..7

    const float* xb = x + (size_t)b * Cc * NA * HW + (size_t)n * HW + pt * 256;

    float acc[8][8];
#pragma unroll
    for (int i = 0; i < 8; i++)
#pragma unroll
        for (int j = 0; j < 8; j++) acc[i][j] = 0.0f;

    for (int kc = 0; kc < Cc; kc += 16) {
        __syncthreads();
        // load x tile: 16 channels x 256 px (coalesced: 256 consecutive floats/row)
#pragma unroll
        for (int r = 0; r < 16; r++)
            xs[r][tid] = xb[(size_t)(kc + r) * (NA * HW) + tid];
        // load W tile: 64 o x 16 c
#pragma unroll
        for (int i = 0; i < 4; i++) {
            int idx = tid + i * 256;    // 0..1023
            int ol = idx >> 4, cl = idx & 15;
            ws[ol][cl] = Wm[(ot * 64 + ol) * Cc + kc + cl];
        }
        __syncthreads();

#pragma unroll
        for (int cl = 0; cl < 16; cl++) {
            float xv[8], wv[8];
#pragma unroll
            for (int jp = 0; jp < 8; jp++) xv[jp] = xs[cl][ptid + 32 * jp];
#pragma unroll
            for (int jo = 0; jo < 8; jo++) wv[jo] = ws[otid * 8 + jo][cl];
#pragma unroll
            for (int jo = 0; jo < 8; jo++)
#pragma unroll
                for (int jp = 0; jp < 8; jp++)
                    acc[jo][jp] += wv[jo] * xv[jp];
        }
    }

    float* ob = g_qkv + (((size_t)b * Oo + ot * 64) * NA + n) * HW + pt * 256;
#pragma unroll
    for (int jo = 0; jo < 8; jo++)
#pragma unroll
        for (int jp = 0; jp < 8; jp++)
            ob[(size_t)(otid * 8 + jo) * (NA * HW) + 32 * jp + ptid] = acc[jo][jp];
}

// ---------------------------------------------------------------------------
// K2: per (b,d) block: partial S[n,m] = sum_p q[d,n,p]*k[d,m,p], plus
// squared-norm partials nq2[n], nk2[m]. Deterministic: slice reduction in
// smem (fixed order), partial written to g_part; cross-d reduction in K3.
// 250 active threads = 25 (5x5 pair tiles) x 10 p-slices.
// ---------------------------------------------------------------------------
__global__ __launch_bounds__(256) void k_gram() {
    const int d = blockIdx.x;           // 0..63
    const int b = blockIdx.y;           // 0..3

    const float* qp = g_qkv + ((size_t)b * Oo + d) * (NA * HW);
    const float* kp = g_qkv + ((size_t)b * Oo + 64 + d) * (NA * HW);

    __shared__ float pool[2 * 25 * 136];          // 6800 floats; overlaid by sred (6750) after loop
    float* qs = pool;                              // [25][136]
    float* ks = pool + 25 * 136;                   // [25][136]

    const int tid   = threadIdx.x;
    const int tile  = tid / 10;                    // 0..24 (valid when tid<250)
    const int slice = tid % 10;
    const int tr = tile / 5, tc = tile % 5;
    const bool active = (tid < 250);

    float acc[5][5];
#pragma unroll
    for (int i = 0; i < 5; i++)
#pragma unroll
        for (int j = 0; j < 5; j++) acc[i][j] = 0.0f;
    float accq[5] = {0, 0, 0, 0, 0};
    float acck[5] = {0, 0, 0, 0, 0};

    for (int p0 = 0; p0 < HW; p0 += 128) {
        __syncthreads();
        for (int i = tid; i < 25 * 128; i += 256) {
            int r = i >> 7, c = i & 127;
            qs[r * 136 + c] = qp[(size_t)r * HW + p0 + c];
            ks[r * 136 + c] = kp[(size_t)r * HW + p0 + c];
        }
        __syncthreads();
        if (active) {
            for (int pp = slice; pp < 128; pp += 10) {
                float qv[5], kv[5];
#pragma unroll
                for (int i = 0; i < 5; i++) qv[i] = qs[(tr * 5 + i) * 136 + pp];
#pragma unroll
                for (int j = 0; j < 5; j++) kv[j] = ks[(tc * 5 + j) * 136 + pp];
#pragma unroll
                for (int i = 0; i < 5; i++)
#pragma unroll
                    for (int j = 0; j < 5; j++)
                        acc[i][j] += qv[i] * kv[j];
                if (tc == 0) {
#pragma unroll
                    for (int i = 0; i < 5; i++) accq[i] += qv[i] * qv[i];
                }
                if (tr == 0) {
#pragma unroll
                    for (int j = 0; j < 5; j++) acck[j] += kv[j] * kv[j];
                }
            }
        }
    }

    __syncthreads();
    float* sred = pool;                            // [675][10] overlay
    if (active) {
#pragma unroll
        for (int i = 0; i < 5; i++)
#pragma unroll
            for (int j = 0; j < 5; j++)
                sred[((tr * 5 + i) * 25 + (tc * 5 + j)) * 10 + slice] = acc[i][j];
        if (tc == 0) {
#pragma unroll
            for (int i = 0; i < 5; i++)
                sred[(625 + tr * 5 + i) * 10 + slice] = accq[i];
        }
        if (tr == 0) {
#pragma unroll
            for (int j = 0; j < 5; j++)
                sred[(650 + tc * 5 + j) * 10 + slice] = acck[j];
        }
    }
    __syncthreads();

    float* gp = g_part + ((size_t)b * Dd + d) * 675;
    for (int e = tid; e < 675; e += 256) {
        float s = 0.0f;
#pragma unroll
        for (int sl = 0; sl < 10; sl++) s += sred[e * 10 + sl];
        gp[e] = s;
    }
}

// ---------------------------------------------------------------------------
// K3: reduce 64 d-partials per batch (fixed order -> deterministic), then
// normalized softmax: att = softmax( S[n,m] / (max(||q_n||,eps)*max(||k_m||,eps)) )
// ---------------------------------------------------------------------------
__global__ __launch_bounds__(256) void k_soft() {
    __shared__ float sS[Bb * 675];
    const int tid = threadIdx.x;

    for (int e = tid; e < Bb * 675; e += 256) {
        int b = e / 675, r = e % 675;
        const float* gp = g_part + (size_t)b * Dd * 675 + r;
        float s = 0.0f;
#pragma unroll 8
        for (int dd = 0; dd < Dd; dd++) s += gp[(size_t)dd * 675];
        sS[e] = s;
    }
    __syncthreads();

    if (tid < Bb * NA) {
        int b = tid / NA, n = tid % NA;
        const float* Sb = sS + b * 675;
        float qn = fmaxf(sqrtf(fmaxf(Sb[625 + n], 0.0f)), 1e-12f);
        float v[25];
        float mx = -3.0e38f;
#pragma unroll
        for (int m = 0; m < 25; m++) {
            float kn = fmaxf(sqrtf(fmaxf(Sb[650 + m], 0.0f)), 1e-12f);
            v[m] = Sb[n * 25 + m] / (qn * kn);
            mx = fmaxf(mx, v[m]);
        }
        float sum = 0.0f;
#pragma unroll
        for (int m = 0; m < 25; m++) {
            v[m] = expf(v[m] - mx);
            sum += v[m];
        }
        float inv = 1.0f / sum;
#pragma unroll
        for (int m = 0; m < 25; m++)
            g_att[(b * NA + n) * NA + m] = v[m] * inv;
    }
}

// ---------------------------------------------------------------------------
// K4: out[b,d,n,p] = sum_m att[b,n,m] * v[b,d,m,p]
// Block: (b, d, ptile of 1024 px). Thread: float4 (4 px) x 5-row n-blocking.
// ---------------------------------------------------------------------------
__global__ __launch_bounds__(256) void k_out(float* __restrict__ out) {
    const int pt = blockIdx.x;          // 0..3
    const int d  = blockIdx.y;          // 0..63
    const int b  = blockIdx.z;          // 0..3

    __shared__ float atts[625];
    const int tid = threadIdx.x;
    for (int i = tid; i < 625; i += 256) atts[i] = g_att[b * 625 + i];
    __syncthreads();

    const int px = pt * 1024 + tid * 4;
    const float4* vp = (const float4*)(g_qkv + (((size_t)b * Oo + 128 + d) * NA) * HW + px);
    float4* op = (float4*)(out + (((size_t)b * Dd + d) * NA) * HW + px);

    for (int ng = 0; ng < 5; ng++) {
        float4 acc[5];
#pragma unroll
        for (int i = 0; i < 5; i++) acc[i] = make_float4(0.f, 0.f, 0.f, 0.f);
#pragma unroll
        for (int m = 0; m < 25; m++) {
            float4 vv = vp[m * (HW / 4)];
#pragma unroll
            for (int i = 0; i < 5; i++) {
                float a = atts[(ng * 5 + i) * 25 + m];
                acc[i].x += a * vv.x;
                acc[i].y += a * vv.y;
                acc[i].z += a * vv.z;
                acc[i].w += a * vv.w;
            }
        }
#pragma unroll
        for (int i = 0; i < 5; i++)
            op[(ng * 5 + i) * (HW / 4)] = acc[i];
    }
}

// ---------------------------------------------------------------------------
extern "C" void kernel_launch(void* const* d_in, const int* in_sizes, int n_in,
                              void* d_out, int out_size) {
    const float* x  = (const float*)d_in[0];
    const float* Wm = (const float*)d_in[1];
    float* out = (float*)d_out;

    k_qkv<<<dim3(16, 75, 4), 256>>>(x, Wm);   // 4800 blocks
    k_gram<<<dim3(64, 4), 256>>>();           // 256 blocks
    k_soft<<<1, 256>>>();
    k_out<<<dim3(4, 64, 4), 256>>>(out);      // 1024 blocks
}

// round 4
// speedup vs baseline: 1.3026x; 1.2886x over previous
#include <cuda_runtime.h>
#include <cuda_bf16.h>
#include <cstdint>

// Problem constants
#define Bb 4
#define Cc 64
#define NA 25
#define HW 4096
#define Dd 64
#define Oo 192

// ---------------------------------------------------------------------------
// Scratch (device globals -- no runtime allocation allowed)
// ---------------------------------------------------------------------------
__device__ float g_qkv[(size_t)Bb * Oo * NA * HW];   // 315 MB fp32 q,k,v
__device__ float g_part[Bb * Dd * 2 * 675];          // per-(b,d,pxhalf) partials
__device__ float g_S[Bb * 675];
__device__ float g_att[Bb * NA * NA];

// ---------------------------------------------------------------------------
// Helpers: ldmatrix + mma.sync (plain sm_80+ PTX -- compiles on compute_103)
// ---------------------------------------------------------------------------
__device__ __forceinline__ uint32_t smem_u32(const void* p) {
    uint32_t a;
    asm("{ .reg .u64 t; cvta.to.shared.u64 t, %1; cvt.u32.u64 %0, t; }" : "=r"(a) : "l"(p));
    return a;
}
#define LDSM_X4(r, addr)                                                       \
    asm volatile("ldmatrix.sync.aligned.m8n8.x4.shared.b16 {%0,%1,%2,%3}, [%4];" \
                 : "=r"((r)[0]), "=r"((r)[1]), "=r"((r)[2]), "=r"((r)[3])      \
                 : "r"(addr))
#define LDSM_X4_T(r, addr)                                                     \
    asm volatile("ldmatrix.sync.aligned.m8n8.x4.trans.shared.b16 {%0,%1,%2,%3}, [%4];" \
                 : "=r"((r)[0]), "=r"((r)[1]), "=r"((r)[2]), "=r"((r)[3])      \
                 : "r"(addr))
__device__ __forceinline__ void mma16816(float* c, const uint32_t* a,
                                         uint32_t b0, uint32_t b1) {
    asm volatile(
        "mma.sync.aligned.m16n8k16.row.col.f32.bf16.bf16.f32 "
        "{%0,%1,%2,%3}, {%4,%5,%6,%7}, {%8,%9}, {%0,%1,%2,%3};"
        : "+f"(c[0]), "+f"(c[1]), "+f"(c[2]), "+f"(c[3])
        : "r"(a[0]), "r"(a[1]), "r"(a[2]), "r"(a[3]), "r"(b0), "r"(b1));
}
__device__ __forceinline__ uint32_t packbf2(float x, float y) {
    __nv_bfloat162 t;
    t.x = __float2bfloat16(x);
    t.y = __float2bfloat16(y);
    return *reinterpret_cast<uint32_t*>(&t);
}

// ---------------------------------------------------------------------------
// K1: qkv[b,o,n,p] = sum_c W[o,c]*x[b,c,n,p] via HMMA bf16 split precision.
// Block = (b, n, pt of 128 px), 256 threads = 8 warps (2 px-rows x 4 o-cols).
// smem (bytes): xs_h[64][136]bf16 @0 (17408), xs_l @17408,
//               ws_h[192][72]bf16 @34816 (27648), ws_l @62464. Total 90112.
// Epilogue reuses smem as css[96][132] fp32 (50688 B).
// ---------------------------------------------------------------------------
#define XSH 0
#define XSL 17408
#define WSH 34816
#define WSL 62464
#define SM_K1 90112
#define XST 136
#define WST 72

__global__ __launch_bounds__(256) void k1_mma(const float* __restrict__ x,
                                              const float* __restrict__ Wm) {
    extern __shared__ char smem[];
    const uint32_t sbase = smem_u32(smem);
    const int tid = threadIdx.x, lane = tid & 31, wid = tid >> 5;
    const int wr = wid >> 2, wc = wid & 3;          // warp px-row, o-col
    const int pt = blockIdx.x, n = blockIdx.y, b = blockIdx.z;

    // ---- load + split x tile: [64 c][128 px] fp32 -> xs_h/xs_l [c][px] bf16
    {
        const float4* xb4 = (const float4*)(x + (size_t)b * Cc * NA * HW
                                            + (size_t)n * HW + pt * 128);
        __nv_bfloat16* xh = (__nv_bfloat16*)(smem + XSH);
        __nv_bfloat16* xl = (__nv_bfloat16*)(smem + XSL);
#pragma unroll
        for (int i = 0; i < 8; i++) {
            int idx = tid + i * 256;                // 0..2047
            int c = idx >> 5, p4 = idx & 31;
            float4 v = xb4[(size_t)c * (NA * HW / 4) + p4];
            uint32_t h0 = packbf2(v.x, v.y), h1 = packbf2(v.z, v.w);
            float rx = v.x - __bfloat162float(((__nv_bfloat162*)&h0)->x);
            float ry = v.y - __bfloat162float(((__nv_bfloat162*)&h0)->y);
            float rz = v.z - __bfloat162float(((__nv_bfloat162*)&h1)->x);
            float rw = v.w - __bfloat162float(((__nv_bfloat162*)&h1)->y);
            uint32_t l0 = packbf2(rx, ry), l1 = packbf2(rz, rw);
            int e = c * XST + p4 * 4;
            *(uint2*)(xh + e) = make_uint2(h0, h1);
            *(uint2*)(xl + e) = make_uint2(l0, l1);
        }
        // ---- load + split W: [192 o][64 c]
        const float4* wb4 = (const float4*)Wm;
        __nv_bfloat16* wh = (__nv_bfloat16*)(smem + WSH);
        __nv_bfloat16* wl = (__nv_bfloat16*)(smem + WSL);
#pragma unroll
        for (int i = 0; i < 12; i++) {
            int idx = tid + i * 256;                // 0..3071
            int o = idx >> 4, c4 = idx & 15;
            float4 v = wb4[idx];
            uint32_t h0 = packbf2(v.x, v.y), h1 = packbf2(v.z, v.w);
            float rx = v.x - __bfloat162float(((__nv_bfloat162*)&h0)->x);
            float ry = v.y - __bfloat162float(((__nv_bfloat162*)&h0)->y);
            float rz = v.z - __bfloat162float(((__nv_bfloat162*)&h1)->x);
            float rw = v.w - __bfloat162float(((__nv_bfloat162*)&h1)->y);
            uint32_t l0 = packbf2(rx, ry), l1 = packbf2(rz, rw);
            int e = o * WST + c4 * 4;
            *(uint2*)(wh + e) = make_uint2(h0, h1);
            *(uint2*)(wl + e) = make_uint2(l0, l1);
        }
    }
    __syncthreads();

    // ---- MMA mainloop: virtual K=192 = [xh|xh|xl] . [wh|wl|wh]
    float acc[4][6][4];
#pragma unroll
    for (int mi = 0; mi < 4; mi++)
#pragma unroll
        for (int ni = 0; ni < 6; ni++)
#pragma unroll
            for (int e = 0; e < 4; e++) acc[mi][ni][e] = 0.0f;

    const int li = lane & 7, sel = lane >> 3;
    const int arow = ((sel & 2) ? 8 : 0) + li;      // k offset
    const int acol = (sel & 1) ? 8 : 0;             // m offset
    const int brow = arow;                          // n offset
    const int bkoff = acol;                         // k offset

    const uint32_t xsel[3] = {XSH, XSH, XSL};
    const uint32_t wsel[3] = {WSH, WSL, WSH};

#pragma unroll
    for (int ch = 0; ch < 3; ch++) {
#pragma unroll
        for (int kk = 0; kk < 4; kk++) {
            const int k0 = kk * 16;
            uint32_t a[4][4];
#pragma unroll
            for (int mi = 0; mi < 4; mi++) {
                uint32_t ad = sbase + xsel[ch]
                    + (uint32_t)(((k0 + arow) * XST) + wr * 64 + mi * 16 + acol) * 2;
                LDSM_X4_T(a[mi], ad);
            }
            uint32_t bf[3][4];
#pragma unroll
            for (int np = 0; np < 3; np++) {
                uint32_t bd = sbase + wsel[ch]
                    + (uint32_t)(((wc * 48 + np * 16 + brow) * WST) + k0 + bkoff) * 2;
                LDSM_X4(bf[np], bd);
            }
#pragma unroll
            for (int mi = 0; mi < 4; mi++)
#pragma unroll
                for (int ni = 0; ni < 6; ni++)
                    mma16816(acc[mi][ni], a[mi],
                             bf[ni >> 1][(ni & 1) * 2], bf[ni >> 1][(ni & 1) * 2 + 1]);
        }
    }

    // ---- epilogue: stage 96 o-rows at a time through smem, coalesced store
    float* css = (float*)smem;                      // [96][132]
    const int g = lane >> 2, t2 = (lane & 3) * 2;
    float* qdst = g_qkv + ((size_t)b * Oo * NA + n) * HW + pt * 128;

#pragma unroll 1
    for (int rnd = 0; rnd < 2; rnd++) {
        __syncthreads();
        if ((wc >> 1) == rnd) {
            const int ob = (wc & 1) * 48;
#pragma unroll
            for (int mi = 0; mi < 4; mi++) {
                const int px = wr * 64 + mi * 16 + g;
#pragma unroll
                for (int ni = 0; ni < 6; ni++) {
                    const int orel = ob + ni * 8 + t2;
                    css[orel * 132 + px] = acc[mi][ni][0];
                    css[(orel + 1) * 132 + px] = acc[mi][ni][1];
                    css[orel * 132 + px + 8] = acc[mi][ni][2];
                    css[(orel + 1) * 132 + px + 8] = acc[mi][ni][3];
                }
            }
        }
        __syncthreads();
#pragma unroll
        for (int i = 0; i < 12; i++) {
            int idx = tid + i * 256;                // 0..3071
            int orel = idx >> 5, p4 = idx & 31;
            const float* s = css + orel * 132 + p4 * 4;
            float4 v = make_float4(s[0], s[1], s[2], s[3]);
            *(float4*)(qdst + (size_t)(rnd * 96 + orel) * (NA * HW) + p4 * 4) = v;
        }
    }
}

// ---------------------------------------------------------------------------
// K2: per (b,d,pxhalf): partial S[n,m] + norm partials. Deterministic.
// ---------------------------------------------------------------------------
__global__ __launch_bounds__(256) void k_gram() {
    const int d = blockIdx.x, half = blockIdx.y, b = blockIdx.z;

    const float* qp = g_qkv + ((size_t)b * Oo + d) * (NA * HW);
    const float* kp = g_qkv + ((size_t)b * Oo + 64 + d) * (NA * HW);

    __shared__ float pool[2 * 25 * 136];
    float* qs = pool;
    float* ks = pool + 25 * 136;

    const int tid = threadIdx.x;
    const int tile = tid / 10, slice = tid % 10;
    const int tr = tile / 5, tc = tile % 5;
    const bool active = (tid < 250);

    float acc[5][5];
#pragma unroll
    for (int i = 0; i < 5; i++)
#pragma unroll
        for (int j = 0; j < 5; j++) acc[i][j] = 0.0f;
    float accq[5] = {0, 0, 0, 0, 0};
    float acck[5] = {0, 0, 0, 0, 0};

    const int pbeg = half * 2048, pend = pbeg + 2048;
    for (int p0 = pbeg; p0 < pend; p0 += 128) {
        __syncthreads();
        for (int i = tid; i < 25 * 128; i += 256) {
            int r = i >> 7, c = i & 127;
            qs[r * 136 + c] = qp[(size_t)r * HW + p0 + c];
            ks[r * 136 + c] = kp[(size_t)r * HW + p0 + c];
        }
        __syncthreads();
        if (active) {
            for (int pp = slice; pp < 128; pp += 10) {
                float qv[5], kv[5];
#pragma unroll
                for (int i = 0; i < 5; i++) qv[i] = qs[(tr * 5 + i) * 136 + pp];
#pragma unroll
                for (int j = 0; j < 5; j++) kv[j] = ks[(tc * 5 + j) * 136 + pp];
#pragma unroll
                for (int i = 0; i < 5; i++)
#pragma unroll
                    for (int j = 0; j < 5; j++)
                        acc[i][j] += qv[i] * kv[j];
                if (tc == 0) {
#pragma unroll
                    for (int i = 0; i < 5; i++) accq[i] += qv[i] * qv[i];
                }
                if (tr == 0) {
#pragma unroll
                    for (int j = 0; j < 5; j++) acck[j] += kv[j] * kv[j];
                }
            }
        }
    }

    __syncthreads();
    float* sred = pool;                            // [675][10] overlay
    if (active) {
#pragma unroll
        for (int i = 0; i < 5; i++)
#pragma unroll
            for (int j = 0; j < 5; j++)
                sred[((tr * 5 + i) * 25 + (tc * 5 + j)) * 10 + slice] = acc[i][j];
        if (tc == 0) {
#pragma unroll
            for (int i = 0; i < 5; i++)
                sred[(625 + tr * 5 + i) * 10 + slice] = accq[i];
        }
        if (tr == 0) {
#pragma unroll
            for (int j = 0; j < 5; j++)
                sred[(650 + tc * 5 + j) * 10 + slice] = acck[j];
        }
    }
    __syncthreads();

    float* gp = g_part + ((size_t)((b * Dd + d) * 2 + half)) * 675;
    for (int e = tid; e < 675; e += 256) {
        float s = 0.0f;
#pragma unroll
        for (int sl = 0; sl < 10; sl++) s += sred[e * 10 + sl];
        gp[e] = s;
    }
}

// ---------------------------------------------------------------------------
// K3a: parallel reduce the 128 (d,half) partials per (b, element).
// ---------------------------------------------------------------------------
__global__ __launch_bounds__(256) void k_red() {
    int e = blockIdx.x * 256 + threadIdx.x;
    if (e >= Bb * 675) return;
    int b = e / 675, r = e % 675;
    const float* gp = g_part + (size_t)b * 128 * 675 + r;
    float s = 0.0f;
#pragma unroll 8
    for (int j = 0; j < 128; j++) s += gp[(size_t)j * 675];
    g_S[e] = s;
}

// K3b: normalize + softmax (tiny)
__global__ __launch_bounds__(128) void k_soft() {
    int tid = threadIdx.x;
    if (tid >= Bb * NA) return;
    int b = tid / NA, n = tid % NA;
    const float* Sb = g_S + b * 675;
    float qn = fmaxf(sqrtf(fmaxf(Sb[625 + n], 0.0f)), 1e-12f);
    float v[25];
    float mx = -3.0e38f;
#pragma unroll
    for (int m = 0; m < 25; m++) {
        float kn = fmaxf(sqrtf(fmaxf(Sb[650 + m], 0.0f)), 1e-12f);
        v[m] = Sb[n * 25 + m] / (qn * kn);
        mx = fmaxf(mx, v[m]);
    }
    float sum = 0.0f;
#pragma unroll
    for (int m = 0; m < 25; m++) {
        v[m] = expf(v[m] - mx);
        sum += v[m];
    }
    float inv = 1.0f / sum;
#pragma unroll
    for (int m = 0; m < 25; m++)
        g_att[(b * NA + n) * NA + m] = v[m] * inv;
}

// ---------------------------------------------------------------------------
// K4: out[b,d,n,p] = sum_m att[b,n,m] * v[b,d,m,p]. m-loop unroll-limited so
// att stays in smem -> higher occupancy.
// ---------------------------------------------------------------------------
__global__ __launch_bounds__(256, 3) void k_out(float* __restrict__ out) {
    const int pt = blockIdx.x;          // 0..3
    const int d  = blockIdx.y;          // 0..63
    const int b  = blockIdx.z;          // 0..3

    __shared__ float atts[625];
    const int tid = threadIdx.x;
    for (int i = tid; i < 625; i += 256) atts[i] = g_att[b * 625 + i];
    __syncthreads();

    const int px = pt * 1024 + tid * 4;
    const float4* vp = (const float4*)(g_qkv + (((size_t)b * Oo + 128 + d) * NA) * HW + px);
    float4* op = (float4*)(out + (((size_t)b * Dd + d) * NA) * HW + px);

#pragma unroll 1
    for (int ng = 0; ng < 5; ng++) {
        float4 acc[5];
#pragma unroll
        for (int i = 0; i < 5; i++) acc[i] = make_float4(0.f, 0.f, 0.f, 0.f);
#pragma unroll 5
        for (int m = 0; m < 25; m++) {
            float4 vv = vp[m * (HW / 4)];
#pragma unroll
            for (int i = 0; i < 5; i++) {
                float a = atts[(ng * 5 + i) * 25 + m];
                acc[i].x += a * vv.x;
                acc[i].y += a * vv.y;
                acc[i].z += a * vv.z;
                acc[i].w += a * vv.w;
            }
        }
#pragma unroll
        for (int i = 0; i < 5; i++)
            op[(ng * 5 + i) * (HW / 4)] = acc[i];
    }
}

// ---------------------------------------------------------------------------
extern "C" void kernel_launch(void* const* d_in, const int* in_sizes, int n_in,
                              void* d_out, int out_size) {
    const float* x  = (const float*)d_in[0];
    const float* Wm = (const float*)d_in[1];
    float* out = (float*)d_out;

    cudaFuncSetAttribute(k1_mma, cudaFuncAttributeMaxDynamicSharedMemorySize, SM_K1);

    k1_mma<<<dim3(32, 25, 4), 256, SM_K1>>>(x, Wm);
    k_gram<<<dim3(64, 2, 4), 256>>>();
    k_red<<<(Bb * 675 + 255) / 256, 256>>>();
    k_soft<<<1, 128>>>();
    k_out<<<dim3(4, 64, 4), 256>>>(out);
}

// round 5
// speedup vs baseline: 2.2060x; 1.6936x over previous
#include <cuda_runtime.h>
#include <cuda_bf16.h>
#include <cstdint>

// Problem constants
#define Bb 4
#define Cc 64
#define NA 25
#define HW 4096
#define Dd 64
#define Oo 192

// ---------------------------------------------------------------------------
// Scratch (device globals -- no runtime allocation allowed)
// ---------------------------------------------------------------------------
__device__ __nv_bfloat16 g_q[(size_t)Bb * NA * HW * Dd];   // [b][n][px][d] 52MB
__device__ __nv_bfloat16 g_k[(size_t)Bb * NA * HW * Dd];   // 52MB
__device__ float g_v[(size_t)Bb * Dd * NA * HW];           // [b][d][n][px] 105MB
__device__ float g_gp[(size_t)Bb * 512 * 1088];            // per-(b,chunk): S 32x32 + qn2 32 + kn2 32
__device__ float g_att[Bb * NA * NA];

// ---------------------------------------------------------------------------
// Helpers: ldmatrix + mma.sync (plain sm_80+ PTX -- compiles on compute_103)
// ---------------------------------------------------------------------------
__device__ __forceinline__ uint32_t smem_u32(const void* p) {
    uint32_t a;
    asm("{ .reg .u64 t; cvta.to.shared.u64 t, %1; cvt.u32.u64 %0, t; }" : "=r"(a) : "l"(p));
    return a;
}
#define LDSM_X4(r, addr)                                                       \
    asm volatile("ldmatrix.sync.aligned.m8n8.x4.shared.b16 {%0,%1,%2,%3}, [%4];" \
                 : "=r"((r)[0]), "=r"((r)[1]), "=r"((r)[2]), "=r"((r)[3])      \
                 : "r"(addr))
#define LDSM_X4_T(r, addr)                                                     \
    asm volatile("ldmatrix.sync.aligned.m8n8.x4.trans.shared.b16 {%0,%1,%2,%3}, [%4];" \
                 : "=r"((r)[0]), "=r"((r)[1]), "=r"((r)[2]), "=r"((r)[3])      \
                 : "r"(addr))
__device__ __forceinline__ void mma16816(float* c, const uint32_t* a,
                                         uint32_t b0, uint32_t b1) {
    asm volatile(
        "mma.sync.aligned.m16n8k16.row.col.f32.bf16.bf16.f32 "
        "{%0,%1,%2,%3}, {%4,%5,%6,%7}, {%8,%9}, {%0,%1,%2,%3};"
        : "+f"(c[0]), "+f"(c[1]), "+f"(c[2]), "+f"(c[3])
        : "r"(a[0]), "r"(a[1]), "r"(a[2]), "r"(a[3]), "r"(b0), "r"(b1));
}
__device__ __forceinline__ uint32_t packbf2(float x, float y) {
    __nv_bfloat162 t;
    t.x = __float2bfloat16(x);
    t.y = __float2bfloat16(y);
    return *reinterpret_cast<uint32_t*>(&t);
}

// ---------------------------------------------------------------------------
// K1: qkv = W x. q,k (o 0..127): single-pass bf16 (xh*wh), written bf16.
//     v (o 128..191): 3-pass split (xh*wh + xh*wl + xl*wh), written fp32.
// Block = (b, n, pt of 128 px), 256 threads = 8 warps.
// smem: xh[64][136] @0, xl @17408, wh[192][72] @34816, wl_v[64][72] @62464.
// ---------------------------------------------------------------------------
#define XSH 0
#define XSL 17408
#define WSH 34816
#define WSL 62464
#define SM_K1 71680
#define XST 136
#define WST 72

__global__ __launch_bounds__(256) void k1_mma(const float* __restrict__ x,
                                              const float* __restrict__ Wm) {
    extern __shared__ char smem[];
    const uint32_t sbase = smem_u32(smem);
    const int tid = threadIdx.x, lane = tid & 31, wid = tid >> 5;
    const int wr = wid >> 2, wc = wid & 3;          // warp px-row (2), o-col (4)
    const int pt = blockIdx.x, n = blockIdx.y, b = blockIdx.z;

    // ---- load + split x tile: [64 c][128 px] fp32 -> xh/xl [c][px] bf16
    {
        const float4* xb4 = (const float4*)(x + (size_t)b * Cc * NA * HW
                                            + (size_t)n * HW + pt * 128);
        __nv_bfloat16* xh = (__nv_bfloat16*)(smem + XSH);
        __nv_bfloat16* xl = (__nv_bfloat16*)(smem + XSL);
#pragma unroll
        for (int i = 0; i < 8; i++) {
            int idx = tid + i * 256;                // 0..2047
            int c = idx >> 5, p4 = idx & 31;
            float4 v = xb4[(size_t)c * (NA * HW / 4) + p4];
            uint32_t h0 = packbf2(v.x, v.y), h1 = packbf2(v.z, v.w);
            float rx = v.x - __bfloat162float(((__nv_bfloat162*)&h0)->x);
            float ry = v.y - __bfloat162float(((__nv_bfloat162*)&h0)->y);
            float rz = v.z - __bfloat162float(((__nv_bfloat162*)&h1)->x);
            float rw = v.w - __bfloat162float(((__nv_bfloat162*)&h1)->y);
            uint32_t l0 = packbf2(rx, ry), l1 = packbf2(rz, rw);
            int e = c * XST + p4 * 4;
            *(uint2*)(xh + e) = make_uint2(h0, h1);
            *(uint2*)(xl + e) = make_uint2(l0, l1);
        }
        // ---- load + split W: hi all 192 rows; lo only v-rows (o>=128)
        const float4* wb4 = (const float4*)Wm;
        __nv_bfloat16* wh = (__nv_bfloat16*)(smem + WSH);
        __nv_bfloat16* wl = (__nv_bfloat16*)(smem + WSL);
#pragma unroll
        for (int i = 0; i < 12; i++) {
            int idx = tid + i * 256;                // 0..3071
            int o = idx >> 4, c4 = idx & 15;
            float4 v = wb4[idx];
            uint32_t h0 = packbf2(v.x, v.y), h1 = packbf2(v.z, v.w);
            *(uint2*)(wh + o * WST + c4 * 4) = make_uint2(h0, h1);
            if (o >= 128) {
                float rx = v.x - __bfloat162float(((__nv_bfloat162*)&h0)->x);
                float ry = v.y - __bfloat162float(((__nv_bfloat162*)&h0)->y);
                float rz = v.z - __bfloat162float(((__nv_bfloat162*)&h1)->x);
                float rw = v.w - __bfloat162float(((__nv_bfloat162*)&h1)->y);
                *(uint2*)(wl + (o - 128) * WST + c4 * 4)
                    = make_uint2(packbf2(rx, ry), packbf2(rz, rw));
            }
        }
    }
    __syncthreads();

    const int li = lane & 7, sel = lane >> 3;
    const int arow = ((sel & 2) ? 8 : 0) + li;      // k row in [k][m] tiles
    const int acol = (sel & 1) ? 8 : 0;             // m offset
    const int brow = arow;                          // n row in [n][k] tiles
    const int bkoff = acol;                         // k offset
    const int g = lane >> 2, t2 = (lane & 3) * 2;

    float acc[4][4][4];

    // ================= Phase A: q,k (o 0..127), single pass =================
#pragma unroll
    for (int mi = 0; mi < 4; mi++)
#pragma unroll
        for (int ni = 0; ni < 4; ni++)
#pragma unroll
            for (int e = 0; e < 4; e++) acc[mi][ni][e] = 0.0f;

#pragma unroll
    for (int kk = 0; kk < 4; kk++) {
        const int k0 = kk * 16;
        uint32_t a[4][4];
#pragma unroll
        for (int mi = 0; mi < 4; mi++)
            LDSM_X4_T(a[mi], sbase + XSH
                + (uint32_t)((k0 + arow) * XST + wr * 64 + mi * 16 + acol) * 2);
        uint32_t bf[2][4];
#pragma unroll
        for (int np = 0; np < 2; np++)
            LDSM_X4(bf[np], sbase + WSH
                + (uint32_t)((wc * 32 + np * 16 + brow) * WST + k0 + bkoff) * 2);
#pragma unroll
        for (int mi = 0; mi < 4; mi++)
#pragma unroll
            for (int ni = 0; ni < 4; ni++)
                mma16816(acc[mi][ni], a[mi],
                         bf[ni >> 1][(ni & 1) * 2], bf[ni >> 1][(ni & 1) * 2 + 1]);
    }

    // Epilogue A: write bf16x2 directly to g_q / g_k ([b][n][px][d])
    {
        __nv_bfloat16* dst = (wc < 2) ? g_q : g_k;
        const int obase = (wc & 1) * 32;
        const size_t rowbase = (size_t)(b * 25 + n) * 4096 + pt * 128;
#pragma unroll
        for (int mi = 0; mi < 4; mi++) {
            const int px = wr * 64 + mi * 16 + g;
#pragma unroll
            for (int ni = 0; ni < 4; ni++) {
                const int o = obase + ni * 8 + t2;
                *(uint32_t*)(dst + (rowbase + px) * 64 + o)
                    = packbf2(acc[mi][ni][0], acc[mi][ni][1]);
                *(uint32_t*)(dst + (rowbase + px + 8) * 64 + o)
                    = packbf2(acc[mi][ni][2], acc[mi][ni][3]);
            }
        }
    }

    // ================= Phase B: v (o 128..191), 3-pass split ================
#pragma unroll
    for (int mi = 0; mi < 4; mi++)
#pragma unroll
        for (int ni = 0; ni < 2; ni++)
#pragma unroll
            for (int e = 0; e < 4; e++) acc[mi][ni][e] = 0.0f;

#pragma unroll
    for (int kk = 0; kk < 4; kk++) {
        const int k0 = kk * 16;
        uint32_t ah[4][4], al[4][4];
#pragma unroll
        for (int mi = 0; mi < 4; mi++) {
            LDSM_X4_T(ah[mi], sbase + XSH
                + (uint32_t)((k0 + arow) * XST + wr * 64 + mi * 16 + acol) * 2);
            LDSM_X4_T(al[mi], sbase + XSL
                + (uint32_t)((k0 + arow) * XST + wr * 64 + mi * 16 + acol) * 2);
        }
        uint32_t bh[4], bl[4];
        LDSM_X4(bh, sbase + WSH
            + (uint32_t)((128 + wc * 16 + brow) * WST + k0 + bkoff) * 2);
        LDSM_X4(bl, sbase + WSL
            + (uint32_t)((wc * 16 + brow) * WST + k0 + bkoff) * 2);
#pragma unroll
        for (int mi = 0; mi < 4; mi++)
#pragma unroll
            for (int ni = 0; ni < 2; ni++) {
                mma16816(acc[mi][ni], ah[mi], bh[ni * 2], bh[ni * 2 + 1]);
                mma16816(acc[mi][ni], ah[mi], bl[ni * 2], bl[ni * 2 + 1]);
                mma16816(acc[mi][ni], al[mi], bh[ni * 2], bh[ni * 2 + 1]);
            }
    }

    // Epilogue B: stage v fp32 via smem (overlays xh/xl region), coalesced out
    __syncthreads();
    float* css = (float*)smem;                      // [64][132]
#pragma unroll
    for (int mi = 0; mi < 4; mi++) {
        const int px = wr * 64 + mi * 16 + g;
#pragma unroll
        for (int ni = 0; ni < 2; ni++) {
            const int orel = wc * 16 + ni * 8 + t2;
            css[orel * 132 + px] = acc[mi][ni][0];
            css[(orel + 1) * 132 + px] = acc[mi][ni][1];
            css[orel * 132 + px + 8] = acc[mi][ni][2];
            css[(orel + 1) * 132 + px + 8] = acc[mi][ni][3];
        }
    }
    __syncthreads();
#pragma unroll
    for (int i = 0; i < 8; i++) {
        int idx = tid + i * 256;                    // 0..2047
        int orel = idx >> 5, p4 = idx & 31;
        const float* s = css + orel * 132 + p4 * 4;
        float4 v = make_float4(s[0], s[1], s[2], s[3]);
        *(float4*)(g_v + ((size_t)(b * 64 + orel) * 25 + n) * 4096
                   + pt * 128 + p4 * 4) = v;
    }
}

// ---------------------------------------------------------------------------
// K2: Gram via HMMA on bf16 q,k. Block = (chunk of 512 f, b).
// f-layout = [px][d] flattened; chunk = 8 px rows x 64 d (contiguous 1KB/n).
// Computes S[32][32] partial + qn2/kn2 norm partials.
// ---------------------------------------------------------------------------
#define GST 520
#define SM_GRAM (2 * 32 * GST * 2)

__global__ __launch_bounds__(128) void k_gram() {
    extern __shared__ char gsm[];
    __nv_bfloat16* qs = (__nv_bfloat16*)gsm;        // [32][520]
    __nv_bfloat16* ks = qs + 32 * GST;
    const int ch = blockIdx.x, b = blockIdx.y;
    const int tid = threadIdx.x, lane = tid & 31, w = tid >> 5;

    // load 25 rows x 512 bf16 per side (rows 25..31 left garbage; never read)
    for (int i = tid; i < 1600; i += 128) {
        int n = i >> 6, j = i & 63;
        ((uint4*)(qs + n * GST))[j]
            = ((const uint4*)g_q)[(size_t)(b * 25 + n) * 32768 + (size_t)ch * 64 + j];
        ((uint4*)(ks + n * GST))[j]
            = ((const uint4*)g_k)[(size_t)(b * 25 + n) * 32768 + (size_t)ch * 64 + j];
    }
    __syncthreads();

    float* gp = g_gp + (size_t)(b * 512 + ch) * 1088;

    // norm partials (fixed order, deterministic)
    if (tid < 50) {
        const int isk = tid >= 25;
        const int n = tid - isk * 25;
        const __nv_bfloat16* r = (isk ? ks : qs) + n * GST;
        float s = 0.0f;
#pragma unroll 8
        for (int f = 0; f < 512; f++) {
            float v = __bfloat162float(r[f]);
            s += v * v;
        }
        gp[1024 + isk * 32 + n] = s;
    }

    // MMA: 4 warps, warp w: m-off=(w&1)*16, n-off=(w>>1)*16
    const int moff = (w & 1) * 16, noff = (w >> 1) * 16;
    const int li = lane & 7, sel = lane >> 3;
    const uint32_t qb = smem_u32(qs), kb = smem_u32(ks);
    const uint32_t aoff = (uint32_t)((moff + ((sel & 1) ? 8 : 0) + li) * GST
                                     + ((sel & 2) ? 8 : 0)) * 2;
    const uint32_t boff = (uint32_t)((noff + ((sel & 2) ? 8 : 0) + li) * GST
                                     + ((sel & 1) ? 8 : 0)) * 2;

    float acc[2][4] = {{0, 0, 0, 0}, {0, 0, 0, 0}};
#pragma unroll 8
    for (int k0 = 0; k0 < 512; k0 += 16) {
        uint32_t a[4], bf[4];
        LDSM_X4(a, qb + aoff + k0 * 2);
        LDSM_X4(bf, kb + boff + k0 * 2);
        mma16816(acc[0], a, bf[0], bf[1]);
        mma16816(acc[1], a, bf[2], bf[3]);
    }

    const int row = moff + (lane >> 2), col0 = noff + (lane & 3) * 2;
#pragma unroll
    for (int ni = 0; ni < 2; ni++) {
        const int col = col0 + ni * 8;
        gp[row * 32 + col] = acc[ni][0];
        gp[row * 32 + col + 1] = acc[ni][1];
        gp[(row + 8) * 32 + col] = acc[ni][2];
        gp[(row + 8) * 32 + col + 1] = acc[ni][3];
    }
}

// ---------------------------------------------------------------------------
// K3: reduce 512 chunk-partials (fixed order) + normalize + softmax. 1 blk/b.
// ---------------------------------------------------------------------------
__global__ __launch_bounds__(704) void k_redsoft() {
    __shared__ float sS[675];
    const int b = blockIdx.x, tid = threadIdx.x;

    if (tid < 675) {
        int idx;
        if (tid < 625) idx = (tid / 25) * 32 + (tid % 25);
        else if (tid < 650) idx = 1024 + (tid - 625);
        else idx = 1056 + (tid - 650);
        const float* gp = g_gp + (size_t)b * 512 * 1088 + idx;
        float s = 0.0f;
#pragma unroll 8
        for (int ch = 0; ch < 512; ch++) s += gp[(size_t)ch * 1088];
        sS[tid] = s;
    }
    __syncthreads();

    if (tid < 25) {
        const int n = tid;
        float qn = fmaxf(sqrtf(fmaxf(sS[625 + n], 0.0f)), 1e-12f);
        float v[25];
        float mx = -3.0e38f;
#pragma unroll
        for (int m = 0; m < 25; m++) {
            float kn = fmaxf(sqrtf(fmaxf(sS[650 + m], 0.0f)), 1e-12f);
            v[m] = sS[n * 25 + m] / (qn * kn);
            mx = fmaxf(mx, v[m]);
        }
        float sum = 0.0f;
#pragma unroll
        for (int m = 0; m < 25; m++) {
            v[m] = expf(v[m] - mx);
            sum += v[m];
        }
        float inv = 1.0f / sum;
#pragma unroll
        for (int m = 0; m < 25; m++)
            g_att[(b * NA + n) * NA + m] = v[m] * inv;
    }
}

// ---------------------------------------------------------------------------
// K4: out[b,d,n,p] = sum_m att[b,n,m] * v[b,d,m,p].
// ---------------------------------------------------------------------------
__global__ __launch_bounds__(256, 3) void k_out(float* __restrict__ out) {
    const int pt = blockIdx.x;          // 0..3
    const int d  = blockIdx.y;          // 0..63
    const int b  = blockIdx.z;          // 0..3

    __shared__ float atts[625];
    const int tid = threadIdx.x;
    for (int i = tid; i < 625; i += 256) atts[i] = g_att[b * 625 + i];
    __syncthreads();

    const int px = pt * 1024 + tid * 4;
    const float4* vp = (const float4*)(g_v + ((size_t)(b * 64 + d) * 25) * 4096 + px);
    float4* op = (float4*)(out + (((size_t)b * Dd + d) * NA) * HW + px);

#pragma unroll 1
    for (int ng = 0; ng < 5; ng++) {
        float4 acc[5];
#pragma unroll
        for (int i = 0; i < 5; i++) acc[i] = make_float4(0.f, 0.f, 0.f, 0.f);
#pragma unroll 5
        for (int m = 0; m < 25; m++) {
            float4 vv = vp[m * (HW / 4)];
#pragma unroll
            for (int i = 0; i < 5; i++) {
                float a = atts[(ng * 5 + i) * 25 + m];
                acc[i].x += a * vv.x;
                acc[i].y += a * vv.y;
                acc[i].z += a * vv.z;
                acc[i].w += a * vv.w;
            }
        }
#pragma unroll
        for (int i = 0; i < 5; i++)
            op[(ng * 5 + i) * (HW / 4)] = acc[i];
    }
}

// ---------------------------------------------------------------------------
extern "C" void kernel_launch(void* const* d_in, const int* in_sizes, int n_in,
                              void* d_out, int out_size) {
    const float* x  = (const float*)d_in[0];
    const float* Wm = (const float*)d_in[1];
    float* out = (float*)d_out;

    cudaFuncSetAttribute(k1_mma, cudaFuncAttributeMaxDynamicSharedMemorySize, SM_K1);
    cudaFuncSetAttribute(k_gram, cudaFuncAttributeMaxDynamicSharedMemorySize, SM_GRAM);

    k1_mma<<<dim3(32, 25, 4), 256, SM_K1>>>(x, Wm);
    k_gram<<<dim3(512, 4), 128, SM_GRAM>>>();
    k_redsoft<<<4, 704>>>();
    k_out<<<dim3(4, 64, 4), 256>>>(out);
}

// round 6
// speedup vs baseline: 2.4334x; 1.1031x over previous
#include <cuda_runtime.h>
#include <cuda_bf16.h>
#include <cstdint>

// Problem constants
#define Bb 4
#define Cc 64
#define NA 25
#define HW 4096
#define Dd 64
#define Oo 192

// ---------------------------------------------------------------------------
// Scratch (device globals -- no runtime allocation allowed)
// ---------------------------------------------------------------------------
__device__ __nv_bfloat16 g_q[(size_t)Bb * NA * HW * Dd];   // [b][n][px][d] 52MB
__device__ __nv_bfloat16 g_k[(size_t)Bb * NA * HW * Dd];   // 52MB
__device__ float g_v[(size_t)Bb * Dd * NA * HW];           // [b][d][n][px] 105MB
__device__ float g_gp[(size_t)Bb * 128 * 1088];            // per-(b,chunk4): S 32x32 + qn2 + kn2
__device__ float g_att[Bb * NA * NA];

// ---------------------------------------------------------------------------
// Helpers: ldmatrix + mma.sync (plain sm_80+ PTX -- compiles on compute_103)
// ---------------------------------------------------------------------------
__device__ __forceinline__ uint32_t smem_u32(const void* p) {
    uint32_t a;
    asm("{ .reg .u64 t; cvta.to.shared.u64 t, %1; cvt.u32.u64 %0, t; }" : "=r"(a) : "l"(p));
    return a;
}
#define LDSM_X4(r, addr)                                                       \
    asm volatile("ldmatrix.sync.aligned.m8n8.x4.shared.b16 {%0,%1,%2,%3}, [%4];" \
                 : "=r"((r)[0]), "=r"((r)[1]), "=r"((r)[2]), "=r"((r)[3])      \
                 : "r"(addr))
#define LDSM_X4_T(r, addr)                                                     \
    asm volatile("ldmatrix.sync.aligned.m8n8.x4.trans.shared.b16 {%0,%1,%2,%3}, [%4];" \
                 : "=r"((r)[0]), "=r"((r)[1]), "=r"((r)[2]), "=r"((r)[3])      \
                 : "r"(addr))
__device__ __forceinline__ void mma16816(float* c, const uint32_t* a,
                                         uint32_t b0, uint32_t b1) {
    asm volatile(
        "mma.sync.aligned.m16n8k16.row.col.f32.bf16.bf16.f32 "
        "{%0,%1,%2,%3}, {%4,%5,%6,%7}, {%8,%9}, {%0,%1,%2,%3};"
        : "+f"(c[0]), "+f"(c[1]), "+f"(c[2]), "+f"(c[3])
        : "r"(a[0]), "r"(a[1]), "r"(a[2]), "r"(a[3]), "r"(b0), "r"(b1));
}
__device__ __forceinline__ uint32_t packbf2(float x, float y) {
    __nv_bfloat162 t;
    t.x = __float2bfloat16(x);
    t.y = __float2bfloat16(y);
    return *reinterpret_cast<uint32_t*>(&t);
}

// ---------------------------------------------------------------------------
// K1: qkv = W x. q,k (o 0..127): single-pass bf16, staged coalesced bf16 out.
//     v (o 128..191): 3-pass split, fp32 out.
// Block = (b, n, pt of 128 px), 256 threads = 8 warps (2 px-rows x 4 o-cols).
// smem: xh[64][136] @0, xl @17408, wh[192][72] @34816, wl_v[64][72] @62464,
//       qs_stage[128][72] bf16 @71680 (18432). Total 90112.
// ---------------------------------------------------------------------------
#define XSH 0
#define XSL 17408
#define WSH 34816
#define WSL 62464
#define QSO 71680
#define SM_K1 90112
#define XST 136
#define WST 72

__global__ __launch_bounds__(256) void k1_mma(const float* __restrict__ x,
                                              const float* __restrict__ Wm) {
    extern __shared__ char smem[];
    const uint32_t sbase = smem_u32(smem);
    const int tid = threadIdx.x, lane = tid & 31, wid = tid >> 5;
    const int wr = wid >> 2, wc = wid & 3;          // warp px-row (2), o-col (4)
    const int pt = blockIdx.x, n = blockIdx.y, b = blockIdx.z;

    // ---- load + split x tile: [64 c][128 px] fp32 -> xh/xl [c][px] bf16
    {
        const float4* xb4 = (const float4*)(x + (size_t)b * Cc * NA * HW
                                            + (size_t)n * HW + pt * 128);
        __nv_bfloat16* xh = (__nv_bfloat16*)(smem + XSH);
        __nv_bfloat16* xl = (__nv_bfloat16*)(smem + XSL);
#pragma unroll
        for (int i = 0; i < 8; i++) {
            int idx = tid + i * 256;                // 0..2047
            int c = idx >> 5, p4 = idx & 31;
            float4 v = xb4[(size_t)c * (NA * HW / 4) + p4];
            uint32_t h0 = packbf2(v.x, v.y), h1 = packbf2(v.z, v.w);
            float rx = v.x - __bfloat162float(((__nv_bfloat162*)&h0)->x);
            float ry = v.y - __bfloat162float(((__nv_bfloat162*)&h0)->y);
            float rz = v.z - __bfloat162float(((__nv_bfloat162*)&h1)->x);
            float rw = v.w - __bfloat162float(((__nv_bfloat162*)&h1)->y);
            uint32_t l0 = packbf2(rx, ry), l1 = packbf2(rz, rw);
            int e = c * XST + p4 * 4;
            *(uint2*)(xh + e) = make_uint2(h0, h1);
            *(uint2*)(xl + e) = make_uint2(l0, l1);
        }
        // ---- load + split W: hi all 192 rows; lo only v-rows (o>=128)
        const float4* wb4 = (const float4*)Wm;
        __nv_bfloat16* wh = (__nv_bfloat16*)(smem + WSH);
        __nv_bfloat16* wl = (__nv_bfloat16*)(smem + WSL);
#pragma unroll
        for (int i = 0; i < 12; i++) {
            int idx = tid + i * 256;                // 0..3071
            int o = idx >> 4, c4 = idx & 15;
            float4 v = wb4[idx];
            uint32_t h0 = packbf2(v.x, v.y), h1 = packbf2(v.z, v.w);
            *(uint2*)(wh + o * WST + c4 * 4) = make_uint2(h0, h1);
            if (o >= 128) {
                float rx = v.x - __bfloat162float(((__nv_bfloat162*)&h0)->x);
                float ry = v.y - __bfloat162float(((__nv_bfloat162*)&h0)->y);
                float rz = v.z - __bfloat162float(((__nv_bfloat162*)&h1)->x);
                float rw = v.w - __bfloat162float(((__nv_bfloat162*)&h1)->y);
                *(uint2*)(wl + (o - 128) * WST + c4 * 4)
                    = make_uint2(packbf2(rx, ry), packbf2(rz, rw));
            }
        }
    }
    __syncthreads();

    const int li = lane & 7, sel = lane >> 3;
    const int arow = ((sel & 2) ? 8 : 0) + li;      // k row in [k][m] tiles
    const int acol = (sel & 1) ? 8 : 0;             // m offset
    const int brow = arow;                          // n row in [n][k] tiles
    const int bkoff = acol;                         // k offset
    const int g = lane >> 2, t2 = (lane & 3) * 2;

    float acc[4][4][4];

    // ================= Phase A: q,k (o 0..127), single pass =================
#pragma unroll
    for (int mi = 0; mi < 4; mi++)
#pragma unroll
        for (int ni = 0; ni < 4; ni++)
#pragma unroll
            for (int e = 0; e < 4; e++) acc[mi][ni][e] = 0.0f;

#pragma unroll
    for (int kk = 0; kk < 4; kk++) {
        const int k0 = kk * 16;
        uint32_t a[4][4];
#pragma unroll
        for (int mi = 0; mi < 4; mi++)
            LDSM_X4_T(a[mi], sbase + XSH
                + (uint32_t)((k0 + arow) * XST + wr * 64 + mi * 16 + acol) * 2);
        uint32_t bf[2][4];
#pragma unroll
        for (int np = 0; np < 2; np++)
            LDSM_X4(bf[np], sbase + WSH
                + (uint32_t)((wc * 32 + np * 16 + brow) * WST + k0 + bkoff) * 2);
#pragma unroll
        for (int mi = 0; mi < 4; mi++)
#pragma unroll
            for (int ni = 0; ni < 4; ni++)
                mma16816(acc[mi][ni], a[mi],
                         bf[ni >> 1][(ni & 1) * 2], bf[ni >> 1][(ni & 1) * 2 + 1]);
    }

    // Epilogue A: stage q then k through padded smem, coalesced bf16 stores
    {
        __nv_bfloat16* qsb = (__nv_bfloat16*)(smem + QSO);
        const size_t rowbase = (size_t)(b * 25 + n) * 4096 + pt * 128;
#pragma unroll 1
        for (int side = 0; side < 2; side++) {
            __syncthreads();
            if ((wc >> 1) == side) {                // wc 0,1 -> q; wc 2,3 -> k
                const int obase = (wc & 1) * 32;
#pragma unroll
                for (int mi = 0; mi < 4; mi++) {
                    const int px = wr * 64 + mi * 16 + g;
#pragma unroll
                    for (int ni = 0; ni < 4; ni++) {
                        const int o = obase + ni * 8 + t2;
                        *(uint32_t*)(qsb + px * 72 + o)
                            = packbf2(acc[mi][ni][0], acc[mi][ni][1]);
                        *(uint32_t*)(qsb + (px + 8) * 72 + o)
                            = packbf2(acc[mi][ni][2], acc[mi][ni][3]);
                    }
                }
            }
            __syncthreads();
            __nv_bfloat16* dst = side ? g_k : g_q;
#pragma unroll
            for (int i = 0; i < 4; i++) {
                int idx = tid + i * 256;            // 0..1023
                int px = idx >> 3, j = idx & 7;
                *(uint4*)(dst + (rowbase + px) * 64 + j * 8)
                    = *(const uint4*)(qsb + px * 72 + j * 8);
            }
        }
    }

    // ================= Phase B: v (o 128..191), 3-pass split ================
#pragma unroll
    for (int mi = 0; mi < 4; mi++)
#pragma unroll
        for (int ni = 0; ni < 2; ni++)
#pragma unroll
            for (int e = 0; e < 4; e++) acc[mi][ni][e] = 0.0f;

#pragma unroll
    for (int kk = 0; kk < 4; kk++) {
        const int k0 = kk * 16;
        uint32_t ah[4][4], al[4][4];
#pragma unroll
        for (int mi = 0; mi < 4; mi++) {
            LDSM_X4_T(ah[mi], sbase + XSH
                + (uint32_t)((k0 + arow) * XST + wr * 64 + mi * 16 + acol) * 2);
            LDSM_X4_T(al[mi], sbase + XSL
                + (uint32_t)((k0 + arow) * XST + wr * 64 + mi * 16 + acol) * 2);
        }
        uint32_t bh[4], bl[4];
        LDSM_X4(bh, sbase + WSH
            + (uint32_t)((128 + wc * 16 + brow) * WST + k0 + bkoff) * 2);
        LDSM_X4(bl, sbase + WSL
            + (uint32_t)((wc * 16 + brow) * WST + k0 + bkoff) * 2);
#pragma unroll
        for (int mi = 0; mi < 4; mi++)
#pragma unroll
            for (int ni = 0; ni < 2; ni++) {
                mma16816(acc[mi][ni], ah[mi], bh[ni * 2], bh[ni * 2 + 1]);
                mma16816(acc[mi][ni], ah[mi], bl[ni * 2], bl[ni * 2 + 1]);
                mma16816(acc[mi][ni], al[mi], bh[ni * 2], bh[ni * 2 + 1]);
            }
    }

    // Epilogue B: stage v fp32 via smem (overlays xh/xl region), coalesced out
    __syncthreads();
    float* css = (float*)smem;                      // [64][132]
#pragma unroll
    for (int mi = 0; mi < 4; mi++) {
        const int px = wr * 64 + mi * 16 + g;
#pragma unroll
        for (int ni = 0; ni < 2; ni++) {
            const int orel = wc * 16 + ni * 8 + t2;
            css[orel * 132 + px] = acc[mi][ni][0];
            css[(orel + 1) * 132 + px] = acc[mi][ni][1];
            css[orel * 132 + px + 8] = acc[mi][ni][2];
            css[(orel + 1) * 132 + px + 8] = acc[mi][ni][3];
        }
    }
    __syncthreads();
#pragma unroll
    for (int i = 0; i < 8; i++) {
        int idx = tid + i * 256;                    // 0..2047
        int orel = idx >> 5, p4 = idx & 31;
        const float* s = css + orel * 132 + p4 * 4;
        float4 v = make_float4(s[0], s[1], s[2], s[3]);
        *(float4*)(g_v + ((size_t)(b * 64 + orel) * 25 + n) * 4096
                   + pt * 128 + p4 * 4) = v;
    }
}

// ---------------------------------------------------------------------------
// K2: Gram via HMMA on bf16 q,k. Block = (chunk4 of 2048 f, b); accumulates
// 4 sub-chunks of 512 f. S[32][32] partial + qn2/kn2 norm partials.
// ---------------------------------------------------------------------------
#define GST 520
#define SM_GRAM (2 * 32 * GST * 2)

__global__ __launch_bounds__(128) void k_gram() {
    extern __shared__ char gsm[];
    __nv_bfloat16* qs = (__nv_bfloat16*)gsm;        // [32][520]
    __nv_bfloat16* ks = qs + 32 * GST;
    const int ch4 = blockIdx.x, b = blockIdx.y;
    const int tid = threadIdx.x, lane = tid & 31, w = tid >> 5;

    const int moff = (w & 1) * 16, noff = (w >> 1) * 16;
    const int li = lane & 7, sel = lane >> 3;
    const uint32_t qb = smem_u32(qs), kb = smem_u32(ks);
    const uint32_t aoff = (uint32_t)((moff + ((sel & 1) ? 8 : 0) + li) * GST
                                     + ((sel & 2) ? 8 : 0)) * 2;
    const uint32_t boff = (uint32_t)((noff + ((sel & 2) ? 8 : 0) + li) * GST
                                     + ((sel & 1) ? 8 : 0)) * 2;

    float acc[2][4] = {{0, 0, 0, 0}, {0, 0, 0, 0}};
    float nsum = 0.0f;
    const int isk = tid >= 25 && tid < 50;
    const int nn = tid - (isk ? 25 : 0);

#pragma unroll 1
    for (int t = 0; t < 4; t++) {
        const int ch = ch4 * 4 + t;
        __syncthreads();
        for (int i = tid; i < 1600; i += 128) {
            int n = i >> 6, j = i & 63;
            ((uint4*)(qs + n * GST))[j]
                = ((const uint4*)g_q)[(size_t)(b * 25 + n) * 32768 + (size_t)ch * 64 + j];
            ((uint4*)(ks + n * GST))[j]
                = ((const uint4*)g_k)[(size_t)(b * 25 + n) * 32768 + (size_t)ch * 64 + j];
        }
        __syncthreads();

        if (tid < 50) {
            const __nv_bfloat16* r = (isk ? ks : qs) + nn * GST;
#pragma unroll 8
            for (int f = 0; f < 512; f++) {
                float v = __bfloat162float(r[f]);
                nsum += v * v;
            }
        }

#pragma unroll 8
        for (int k0 = 0; k0 < 512; k0 += 16) {
            uint32_t a[4], bf[4];
            LDSM_X4(a, qb + aoff + k0 * 2);
            LDSM_X4(bf, kb + boff + k0 * 2);
            mma16816(acc[0], a, bf[0], bf[1]);
            mma16816(acc[1], a, bf[2], bf[3]);
        }
    }

    float* gp = g_gp + (size_t)(b * 128 + ch4) * 1088;
    if (tid < 50) gp[1024 + isk * 32 + nn] = nsum;

    const int row = moff + (lane >> 2), col0 = noff + (lane & 3) * 2;
#pragma unroll
    for (int ni = 0; ni < 2; ni++) {
        const int col = col0 + ni * 8;
        gp[row * 32 + col] = acc[ni][0];
        gp[row * 32 + col + 1] = acc[ni][1];
        gp[(row + 8) * 32 + col] = acc[ni][2];
        gp[(row + 8) * 32 + col + 1] = acc[ni][3];
    }
}

// ---------------------------------------------------------------------------
// K3: reduce 128 chunk-partials (fixed order) + normalize + softmax. 1 blk/b.
// ---------------------------------------------------------------------------
__global__ __launch_bounds__(704) void k_redsoft() {
    __shared__ float sS[675];
    const int b = blockIdx.x, tid = threadIdx.x;

    if (tid < 675) {
        int idx;
        if (tid < 625) idx = (tid / 25) * 32 + (tid % 25);
        else if (tid < 650) idx = 1024 + (tid - 625);
        else idx = 1056 + (tid - 650);
        const float* gp = g_gp + (size_t)b * 128 * 1088 + idx;
        float s = 0.0f;
#pragma unroll 8
        for (int ch = 0; ch < 128; ch++) s += gp[(size_t)ch * 1088];
        sS[tid] = s;
    }
    __syncthreads();

    if (tid < 25) {
        const int n = tid;
        float qn = fmaxf(sqrtf(fmaxf(sS[625 + n], 0.0f)), 1e-12f);
        float v[25];
        float mx = -3.0e38f;
#pragma unroll
        for (int m = 0; m < 25; m++) {
            float kn = fmaxf(sqrtf(fmaxf(sS[650 + m], 0.0f)), 1e-12f);
            v[m] = sS[n * 25 + m] / (qn * kn);
            mx = fmaxf(mx, v[m]);
        }
        float sum = 0.0f;
#pragma unroll
        for (int m = 0; m < 25; m++) {
            v[m] = expf(v[m] - mx);
            sum += v[m];
        }
        float inv = 1.0f / sum;
#pragma unroll
        for (int m = 0; m < 25; m++)
            g_att[(b * NA + n) * NA + m] = v[m] * inv;
    }
}

// ---------------------------------------------------------------------------
// K4: out[b,d,n,p] = sum_m att[b,n,m] * v[b,d,m,p].
// 25 accumulators per thread: v read exactly once from DRAM.
// ---------------------------------------------------------------------------
__global__ __launch_bounds__(128) void k_out(float* __restrict__ out) {
    const int pt = blockIdx.x;          // 0..7
    const int d  = blockIdx.y;          // 0..63
    const int b  = blockIdx.z;          // 0..3

    __shared__ float atts[625];
    const int tid = threadIdx.x;
    for (int i = tid; i < 625; i += 128) atts[i] = g_att[b * 625 + i];
    __syncthreads();

    const int px = pt * 512 + tid * 4;
    const float4* vp = (const float4*)(g_v + ((size_t)(b * 64 + d) * 25) * 4096 + px);
    float4* op = (float4*)(out + ((size_t)(b * 64 + d) * 25) * 4096 + px);

    float4 acc[25];
#pragma unroll
    for (int n = 0; n < 25; n++) acc[n] = make_float4(0.f, 0.f, 0.f, 0.f);

#pragma unroll
    for (int m = 0; m < 25; m++) {
        float4 vv = vp[m * 1024];
#pragma unroll
        for (int n = 0; n < 25; n++) {
            float a = atts[n * 25 + m];
            acc[n].x += a * vv.x;
            acc[n].y += a * vv.y;
            acc[n].z += a * vv.z;
            acc[n].w += a * vv.w;
        }
    }
#pragma unroll
    for (int n = 0; n < 25; n++) op[n * 1024] = acc[n];
}

// ---------------------------------------------------------------------------
extern "C" void kernel_launch(void* const* d_in, const int* in_sizes, int n_in,
                              void* d_out, int out_size) {
    const float* x  = (const float*)d_in[0];
    const float* Wm = (const float*)d_in[1];
    float* out = (float*)d_out;

    cudaFuncSetAttribute(k1_mma, cudaFuncAttributeMaxDynamicSharedMemorySize, SM_K1);
    cudaFuncSetAttribute(k_gram, cudaFuncAttributeMaxDynamicSharedMemorySize, SM_GRAM);

    k1_mma<<<dim3(32, 25, 4), 256, SM_K1>>>(x, Wm);
    k_gram<<<dim3(128, 4), 128, SM_GRAM>>>();
    k_redsoft<<<4, 704>>>();
    k_out<<<dim3(8, 64, 4), 128>>>(out);
}